// round 1
// baseline (speedup 1.0000x reference)
#include <cuda_runtime.h>

#define B_DIM 16
#define G_DIM 1708
#define H_DIM 5
#define NC 27          // Taylor terms n = 0..26
#define NTHREADS 256
#define NWARPS 8

// Per-head scratch: [H][B][G], deterministic combine (no float atomics).
__device__ float g_head[H_DIM * B_DIM * G_DIM];

__constant__ float c_invfact[NC] = {
    1.0f, 1.0f, 0.5f,
    1.6666666666666666e-01f, 4.1666666666666664e-02f, 8.3333333333333332e-03f,
    1.3888888888888889e-03f, 1.9841269841269841e-04f, 2.4801587301587302e-05f,
    2.7557319223985893e-06f, 2.7557319223985894e-07f, 2.5052108385441720e-08f,
    2.0876756987868100e-09f, 1.6059043836821616e-10f, 1.1470745597729726e-11f,
    7.6471637318198174e-13f, 4.7794773323873859e-14f, 2.8114572543455210e-15f,
    1.5619206968586228e-16f, 8.2206352466243295e-18f, 4.1103176233121648e-19f,
    1.9572941063391263e-20f, 8.8967913924505741e-22f, 3.8681701706306840e-23f,
    1.6117375710961184e-24f, 6.4469502843844736e-26f, 2.4795962632247976e-27f };

// One CTA per (batch b, head h).
// out_row[i] = (num(q_i) - exp(q_i*k_i)*v_i) / den(q_i)
// den(u) = sum_j exp(u*k_j),  num(u) = sum_j exp(u*k_j)*v_j
// evaluated via moment expansion: den(u) = sum_n (S_n/n!) u^n,  S_n = sum_j k_j^n
//                                 num(u) = sum_n (M_n/n!) u^n,  M_n = sum_j k_j^n v_j
__global__ __launch_bounds__(NTHREADS, 1)
void attn_heads_kernel(const float* __restrict__ x,  const float* __restrict__ WQ,
                       const float* __restrict__ WK, const float* __restrict__ WV) {
    const int b = blockIdx.x;
    const int h = blockIdx.y;

    __shared__ float sq[G_DIM], sk[G_DIM], sv[G_DIM];
    __shared__ float wS[NWARPS][NC], wM[NWARPS][NC];
    __shared__ float cS[NC], cM[NC];
    __shared__ float wkmax[NWARPS], wkmin[NWARPS];
    __shared__ float s_kmax, s_kmin;

    const int tid = threadIdx.x;
    const float* __restrict__ xb = x  + b * G_DIM;
    const float* __restrict__ wq = WQ + h * G_DIM;
    const float* __restrict__ wk = WK + h * G_DIM;
    const float* __restrict__ wv = WV + h * G_DIM;

    // Stage q/k/v for this (b,h) into smem.
    for (int j = tid; j < G_DIM; j += NTHREADS) {
        float xv = xb[j];
        sq[j] = xv * wq[j];
        sk[j] = xv * wk[j];
        sv[j] = xv * wv[j];
    }
    __syncthreads();

    // Per-thread moment partials.
    float S[NC], M[NC];
#pragma unroll
    for (int n = 0; n < NC; n++) { S[n] = 0.f; M[n] = 0.f; }
    float kmax = -1e30f, kmin = 1e30f;

    for (int j = tid; j < G_DIM; j += NTHREADS) {
        float k = sk[j];
        float v = sv[j];
        kmax = fmaxf(kmax, k);
        kmin = fminf(kmin, k);
        float p = 1.f;
#pragma unroll
        for (int n = 0; n < NC; n++) {
            S[n] += p;
            M[n] = fmaf(p, v, M[n]);
            p *= k;
        }
    }

    // Warp butterfly reduce.
#pragma unroll
    for (int n = 0; n < NC; n++) {
#pragma unroll
        for (int o = 16; o > 0; o >>= 1) {
            S[n] += __shfl_xor_sync(0xffffffffu, S[n], o);
            M[n] += __shfl_xor_sync(0xffffffffu, M[n], o);
        }
    }
    for (int o = 16; o > 0; o >>= 1) {
        kmax = fmaxf(kmax, __shfl_xor_sync(0xffffffffu, kmax, o));
        kmin = fminf(kmin, __shfl_xor_sync(0xffffffffu, kmin, o));
    }

    const int wid = tid >> 5, lane = tid & 31;
    if (lane == 0) {
#pragma unroll
        for (int n = 0; n < NC; n++) { wS[wid][n] = S[n]; wM[wid][n] = M[n]; }
        wkmax[wid] = kmax;
        wkmin[wid] = kmin;
    }
    __syncthreads();

    // Cross-warp finalize: coefficients c_n = (Σ partials) / n!
    if (tid < NC) {
        float s = 0.f;
        for (int w = 0; w < NWARPS; w++) s += wS[w][tid];
        cS[tid] = s * c_invfact[tid];
    } else if (tid < 2 * NC) {
        const int n = tid - NC;
        float s = 0.f;
        for (int w = 0; w < NWARPS; w++) s += wM[w][n];
        cM[n] = s * c_invfact[n];
    } else if (tid == 2 * NC) {
        float a = -1e30f, c = 1e30f;
        for (int w = 0; w < NWARPS; w++) {
            a = fmaxf(a, wkmax[w]);
            c = fminf(c, wkmin[w]);
        }
        s_kmax = a;
        s_kmin = c;
    }
    __syncthreads();

    const float kam = fmaxf(fabsf(s_kmax), fabsf(s_kmin));
    float* __restrict__ dst = g_head + (h * B_DIM + b) * G_DIM;

    // Per-row evaluation.
    for (int i = tid; i < G_DIM; i += NTHREADS) {
        const float u = sq[i];
        float o;
        if (fabsf(u) * kam <= 6.0f) {
            // Dual Horner: den & num (independent chains, good ILP).
            float den = cS[NC - 1];
            float num = cM[NC - 1];
#pragma unroll
            for (int n = NC - 2; n >= 0; n--) {
                den = fmaf(den, u, cS[n]);
                num = fmaf(num, u, cM[n]);
            }
            const float eii = __expf(u * sk[i]);           // diagonal, masked post-softmax
            o = (num - eii * sv[i]) / den;
        } else {
            // Exact fallback (max-subtracted for stability); should not trigger on this data.
            const float m = (u > 0.f) ? u * s_kmax : u * s_kmin;
            float s1 = 0.f, s2 = 0.f;
            for (int j = 0; j < G_DIM; j++) {
                const float e = __expf(fmaf(u, sk[j], -m));
                s1 += e;
                s2 = fmaf(e, sv[j], s2);
            }
            const float eii = __expf(fmaf(u, sk[i], -m));
            o = (s2 - eii * sv[i]) / s1;
        }
        dst[i] = o;
    }
}

// out[b,g] = sum_h W0[h] * head[h,b,g]
__global__ void combine_kernel(const float* __restrict__ W0, float* __restrict__ out) {
    const int idx = blockIdx.x * blockDim.x + threadIdx.x;
    if (idx >= B_DIM * G_DIM) return;
    float acc = 0.f;
#pragma unroll
    for (int h = 0; h < H_DIM; h++)
        acc = fmaf(W0[h], g_head[h * B_DIM * G_DIM + idx], acc);
    out[idx] = acc;
}

extern "C" void kernel_launch(void* const* d_in, const int* in_sizes, int n_in,
                              void* d_out, int out_size) {
    const float* x  = (const float*)d_in[0];
    const float* WQ = (const float*)d_in[1];
    const float* WK = (const float*)d_in[2];
    const float* WV = (const float*)d_in[3];
    const float* W0 = (const float*)d_in[4];
    float* out = (float*)d_out;

    dim3 grid(B_DIM, H_DIM);
    attn_heads_kernel<<<grid, NTHREADS>>>(x, WQ, WK, WV);

    const int n = B_DIM * G_DIM;
    combine_kernel<<<(n + 255) / 256, 256>>>(W0, out);
}